// round 14
// baseline (speedup 1.0000x reference)
#include <cuda_runtime.h>
#include <cuda_bf16.h>
#include <cstdint>

#define Bn 128
#define Sn 2048
#define Hn 512
#define OUTD 32
#define KX0 544
#define G4 2048

// ---------------- scratch globals ----------------------------------------------
__device__ __align__(16) __nv_bfloat16 g_We_hi[Hn * Hn];   // [h][k]
__device__ __align__(16) __nv_bfloat16 g_We_lo[Hn * Hn];
__device__ __align__(16) uint32_t g_enc_hi[Bn * Sn * Hn / 2];  // bf16x2 packed
__device__ __align__(16) uint32_t g_enc_lo[Bn * Sn * Hn / 2];
__device__ int g_flag[4 * 2 * Bn];                          // [region][quarter]
__device__ __align__(16) float g_hpre[Bn * Hn];
__device__ __align__(16) float g_scores[4 * Bn * Sn];      // 4 n-quarter partials
__device__ __align__(16) float g_ctxp[4 * Bn * Hn];
__device__ __align__(16) float g_xstep[Bn * KX0];
__device__ __align__(16) float g_gates[Bn * G4];

// ---------------- math helpers ---------------------------------------------------
__device__ __forceinline__ float ex2f(float x) {
    float r; asm("ex2.approx.f32 %0, %1;" : "=f"(r) : "f"(x)); return r;
}
__device__ __forceinline__ float rcpf(float x) {
    float r; asm("rcp.approx.f32 %0, %1;" : "=f"(r) : "f"(x)); return r;
}
__device__ __forceinline__ float tanh_fast(float x) {
    float e = ex2f(x * 2.885390081777927f);
    return 1.0f - 2.0f * rcpf(e + 1.0f);
}
__device__ __forceinline__ float sigf(float x) {
    return rcpf(1.0f + ex2f(-1.4426950408889634f * x));
}
// pack (a,b) -> bf16x2, a in LOW 16 bits
__device__ __forceinline__ uint32_t bf2(float a, float b) {
    uint32_t r; asm("cvt.rn.bf16x2.f32 %0, %1, %2;" : "=r"(r) : "f"(b), "f"(a)); return r;
}
__device__ __forceinline__ uint32_t smem_u32(const void* p) {
    uint32_t a;
    asm("{ .reg .u64 t; cvta.to.shared.u64 t, %1; cvt.u32.u64 %0, t; }" : "=r"(a) : "l"(p));
    return a;
}
__device__ __forceinline__ uint32_t swz128(uint32_t off) { return off ^ ((off >> 3) & 0x70); }

#define CP16(d, s) asm volatile("cp.async.ca.shared.global [%0], [%1], 16;" :: "r"(d), "l"(s))
#define CP_COMMIT() asm volatile("cp.async.commit_group;" ::: "memory")

#define LDSM4(r, a) \
    asm volatile("ldmatrix.sync.aligned.m8n8.x4.shared.b16 {%0,%1,%2,%3}, [%4];" \
        : "=r"((r)[0]), "=r"((r)[1]), "=r"((r)[2]), "=r"((r)[3]) : "r"(a))
#define MMA16816(c, a, b) \
    asm volatile("mma.sync.aligned.m16n8k16.row.col.f32.bf16.bf16.f32 " \
        "{%0,%1,%2,%3}, {%4,%5,%6,%7}, {%8,%9}, {%0,%1,%2,%3};" \
        : "+f"((c)[0]), "+f"((c)[1]), "+f"((c)[2]), "+f"((c)[3]) \
        : "r"((a)[0]), "r"((a)[1]), "r"((a)[2]), "r"((a)[3]), "r"((b)[0]), "r"((b)[1]))

// ---------------- prep kernels ---------------------------------------------------
__global__ void wesplit_kernel(const float* __restrict__ attn_W) {
    int h = blockIdx.x, k = threadIdx.x;
    float x = attn_W[h * 1024 + 512 + k];
    __nv_bfloat16 hi = __float2bfloat16(x);
    g_We_hi[h * Hn + k] = hi;
    g_We_lo[h * Hn + k] = __float2bfloat16(x - __bfloat162float(hi));
}
__global__ void zeroflags_kernel() {
    g_flag[threadIdx.x] = 0;
}

// ---------------- hpre = h0[1] @ W_h^T + attn_b ----------------------------------
__global__ void hpre_kernel(const float* __restrict__ h0, const float* __restrict__ attn_W,
                            const float* __restrict__ attn_b) {
    __shared__ float sh[Hn];
    int b = blockIdx.x, t = threadIdx.x;
    sh[t] = h0[Bn * Hn + b * Hn + t];
    __syncthreads();
    const float4* w = (const float4*)(attn_W + (size_t)t * 1024);
    float acc = attn_b[t];
#pragma unroll 8
    for (int k4 = 0; k4 < 128; k4++) {
        float4 ww = w[k4];
        acc += sh[k4 * 4 + 0] * ww.x + sh[k4 * 4 + 1] * ww.y
             + sh[k4 * 4 + 2] * ww.z + sh[k4 * 4 + 3] * ww.w;
    }
    g_hpre[b * Hn + t] = acc;
}

// ---------------- scores: mma.sync bf16 3-pass + cooperative enc split -----------
// CTA (ntile 0..3, sgroup 0..1, b): converts stile-ntile's enc rows, flags, waits
// for region's 4 flags, then loops 4 stiles. Per stile: M=256 x N=128, K=512 in
// 8 chunks of 64. 16 warps 4x4: warp tile 64x32.
// SMEM stage st at st*98304: Ahi 32K | Alo 32K | Bhi 16K | Blo 16K
// misc @196608: v[128] | hpre[128] | row[256]
#define SC_SMEM 198656

__global__ __launch_bounds__(512, 1) void scores_mma_kernel(const float* __restrict__ enc,
                                                            const float* __restrict__ v) {
    extern __shared__ __align__(1024) char smem[];
    uint32_t sb = smem_u32(smem);
    int tid = threadIdx.x;
    int lane = tid & 31, wid = tid >> 5;
    int wm = wid >> 2, wn = wid & 3;
    int ntile = blockIdx.x;          // 0..3
    int sgrp  = blockIdx.y;          // 0..1
    int b = blockIdx.z;
    int h0 = ntile * 128;

    float* sh_v    = (float*)(smem + 196608);
    float* sh_hpre = (float*)(smem + 196608 + 512);
    float* sh_row  = (float*)(smem + 196608 + 1024);

    if (tid < 128) {
        sh_v[tid]    = v[h0 + tid];
        sh_hpre[tid] = g_hpre[b * Hn + h0 + tid];
    }
    if (tid < 256) sh_row[tid] = 0.0f;

    // ---- cooperative enc split: this CTA converts stile 'ntile' of its region ----
    int* fl = g_flag + (sgrp * Bn + b) * 4;
    {
        size_t rowbase = (size_t)b * Sn + (size_t)(sgrp * 4 + ntile) * 256;
        const float4* src = (const float4*)enc + rowbase * 128;   // 128 f4 per row
        uint2* dh = (uint2*)g_enc_hi + rowbase * 128;             // 128 uint2 per row
        uint2* dl = (uint2*)g_enc_lo + rowbase * 128;
#pragma unroll 4
        for (int i = tid; i < 32768; i += 512) {
            float4 f = src[i];
            __nv_bfloat16 hx = __float2bfloat16(f.x), hy = __float2bfloat16(f.y);
            __nv_bfloat16 hz = __float2bfloat16(f.z), hw = __float2bfloat16(f.w);
            uint32_t hi0 = bf2(__bfloat162float(hx), __bfloat162float(hy));
            uint32_t hi1 = bf2(__bfloat162float(hz), __bfloat162float(hw));
            uint32_t lo0 = bf2(f.x - __bfloat162float(hx), f.y - __bfloat162float(hy));
            uint32_t lo1 = bf2(f.z - __bfloat162float(hz), f.w - __bfloat162float(hw));
            dh[i] = make_uint2(hi0, hi1);
            dl[i] = make_uint2(lo0, lo1);
        }
        __syncthreads();           // CTA-scope mem barrier: all quarter writes done
        if (tid == 0) {
            __threadfence();       // publish to GPU scope
            atomicExch(&fl[ntile], 1);
            while (atomicAdd(&fl[0], 0) == 0 || atomicAdd(&fl[1], 0) == 0 ||
                   atomicAdd(&fl[2], 0) == 0 || atomicAdd(&fl[3], 0) == 0) { }
        }
        __syncthreads();           // whole CTA sees region ready
    }

    const char* WH = (const char*)(g_We_hi + (size_t)h0 * Hn);
    const char* WL = (const char*)(g_We_lo + (size_t)h0 * Hn);

    auto encbase = [&](int it) -> size_t {
        int s0 = (sgrp * 4 + it) * 256;
        return ((size_t)(b * Sn + s0)) * 1024;   // bytes into packed hi/lo arrays
    };

    auto produce = [&](int it, int c, int st) {
        uint32_t stb = sb + st * 98304;
        uint32_t aH = stb, aL = stb + 32768, bH = stb + 65536, bL = stb + 81920;
        int cb = c * 128;
        const char* EH = (const char*)g_enc_hi + encbase(it);
        const char* EL = (const char*)g_enc_lo + encbase(it);
#pragma unroll
        for (int j = 0; j < 4; j++) {
            int idx = tid + j * 512;           // 0..2047
            int r = idx >> 3, seg = idx & 7;
            uint32_t doff = swz128((uint32_t)(r * 128 + seg * 16));
            CP16(aH + doff, EH + (size_t)r * 1024 + cb + seg * 16);
            CP16(aL + doff, EL + (size_t)r * 1024 + cb + seg * 16);
        }
#pragma unroll
        for (int j = 0; j < 2; j++) {
            int idx = tid + j * 512;           // 0..1023
            int r = idx >> 3, seg = idx & 7;
            uint32_t doff = swz128((uint32_t)(r * 128 + seg * 16));
            CP16(bH + doff, WH + (size_t)r * 1024 + cb + seg * 16);
            CP16(bL + doff, WL + (size_t)r * 1024 + cb + seg * 16);
        }
        CP_COMMIT();
    };

    int arow = lane & 15;
    int acol = (lane >> 4) * 16;
    int brow4 = ((lane >> 4) << 3) | (lane & 7);   // 0..15 row within nf-pair
    int bcol  = ((lane >> 3) & 1) * 16;
    int rbase = lane >> 2;
    int q = lane & 3;
    int cbase = q * 2;

    int kctr = 0;
    produce(0, 0, 0);

    for (int it = 0; it < 4; it++) {
        float acc[4][4][4];
#pragma unroll
        for (int mf = 0; mf < 4; mf++)
#pragma unroll
            for (int nf = 0; nf < 4; nf++)
#pragma unroll
                for (int r = 0; r < 4; r++) acc[mf][nf][r] = 0.0f;

        for (int c = 0; c < 8; c++) {
            int st = kctr & 1;
            asm volatile("cp.async.wait_group 0;" ::: "memory");
            __syncthreads();

            uint32_t stb = sb + st * 98304;
            uint32_t aH = stb, aL = stb + 32768, bH = stb + 65536, bL = stb + 81920;
#pragma unroll
            for (int ks = 0; ks < 4; ks++) {
                uint32_t bh[4][2], bl[4][2];
#pragma unroll
                for (int p = 0; p < 2; p++) {    // nf pairs {0,1}, {2,3}
                    uint32_t off = swz128((uint32_t)((wn * 32 + p * 16 + brow4) * 128 + ks * 32 + bcol));
                    uint32_t t4[4];
                    LDSM4(t4, bH + off);
                    bh[2 * p][0] = t4[0]; bh[2 * p][1] = t4[1];
                    bh[2 * p + 1][0] = t4[2]; bh[2 * p + 1][1] = t4[3];
                    LDSM4(t4, bL + off);
                    bl[2 * p][0] = t4[0]; bl[2 * p][1] = t4[1];
                    bl[2 * p + 1][0] = t4[2]; bl[2 * p + 1][1] = t4[3];
                }
#pragma unroll
                for (int mf = 0; mf < 4; mf++) {
                    uint32_t ah[4], al[4];
                    uint32_t off = swz128((uint32_t)((wm * 64 + mf * 16 + arow) * 128 + ks * 32 + acol));
                    LDSM4(ah, aH + off);
                    LDSM4(al, aL + off);
#pragma unroll
                    for (int nf = 0; nf < 4; nf++) MMA16816(acc[mf][nf], ah, bh[nf]);
#pragma unroll
                    for (int nf = 0; nf < 4; nf++) MMA16816(acc[mf][nf], ah, bl[nf]);
#pragma unroll
                    for (int nf = 0; nf < 4; nf++) MMA16816(acc[mf][nf], al, bh[nf]);
                }
                if (ks == 0) {     // producer hidden under MMAs
                    if (c + 1 < 8)       produce(it, c + 1, st ^ 1);
                    else if (it + 1 < 4) produce(it + 1, 0, st ^ 1);
                }
            }
            kctr++;
        }

        // ---- epilogue for this stile ----
        int s0 = (sgrp * 4 + it) * 256;
        __syncthreads();
#pragma unroll
        for (int mf = 0; mf < 4; mf++) {
#pragma unroll
            for (int rr = 0; rr < 2; rr++) {
                int m = wm * 64 + mf * 16 + rbase + rr * 8;
                float p = 0.0f;
#pragma unroll
                for (int nf = 0; nf < 4; nf++) {
                    int n0 = wn * 32 + nf * 8 + cbase;
                    float e0 = acc[mf][nf][rr * 2 + 0] + sh_hpre[n0];
                    float e1 = acc[mf][nf][rr * 2 + 1] + sh_hpre[n0 + 1];
                    p += sh_v[n0] * tanh_fast(e0) + sh_v[n0 + 1] * tanh_fast(e1);
                }
                p += __shfl_xor_sync(0xffffffffu, p, 1);
                p += __shfl_xor_sync(0xffffffffu, p, 2);
                if (q == 0) atomicAdd(&sh_row[m], p);
            }
        }
        __syncthreads();
        if (tid < 256) {
            g_scores[(size_t)ntile * Bn * Sn + (size_t)b * Sn + s0 + tid] = sh_row[tid];
            sh_row[tid] = 0.0f;
        }
    }
}

// ---------------- softmax (sums the 4 n-quarter partials) ------------------------
__global__ void softmax_kernel(float* __restrict__ out_attn) {
    int b = blockIdx.x, t = threadIdx.x;
    float vals[8];
    float m = -1e30f;
#pragma unroll
    for (int i = 0; i < 8; i++) {
        int idx = t + i * 256;
        vals[i] = g_scores[b * Sn + idx]
                + g_scores[Bn * Sn + b * Sn + idx]
                + g_scores[2 * Bn * Sn + b * Sn + idx]
                + g_scores[3 * Bn * Sn + b * Sn + idx];
        m = fmaxf(m, vals[i]);
    }
    __shared__ float red[256];
    red[t] = m; __syncthreads();
    for (int o = 128; o > 0; o >>= 1) {
        if (t < o) red[t] = fmaxf(red[t], red[t + o]);
        __syncthreads();
    }
    m = red[0];
    __syncthreads();
    float sum = 0.f;
#pragma unroll
    for (int i = 0; i < 8; i++) {
        vals[i] = ex2f((vals[i] - m) * 1.4426950408889634f);
        sum += vals[i];
    }
    red[t] = sum; __syncthreads();
    for (int o = 128; o > 0; o >>= 1) {
        if (t < o) red[t] += red[t + o];
        __syncthreads();
    }
    float inv = 1.0f / red[0];
#pragma unroll
    for (int i = 0; i < 8; i++) out_attn[b * Sn + t + i * 256] = vals[i] * inv;
}

// ---------------- context --------------------------------------------------------
__global__ void context_kernel(const float* __restrict__ enc, const float* __restrict__ attn) {
    int sc = blockIdx.x, b = blockIdx.y, h = threadIdx.x;
    __shared__ float w[512];
    w[h] = attn[b * Sn + sc * 512 + h];
    __syncthreads();
    const float* e = enc + ((size_t)(b * Sn + sc * 512)) * Hn + h;
    float acc = 0.f;
#pragma unroll 8
    for (int s = 0; s < 512; s++) acc += w[s] * e[(size_t)s * Hn];
    g_ctxp[(sc * Bn + b) * Hn + h] = acc;
}
__global__ void xstep_kernel(const float* __restrict__ x) {
    int b = blockIdx.x, t = threadIdx.x;
    float val;
    if (t < OUTD) val = x[b * OUTD + t];
    else {
        int h = t - OUTD;
        val = g_ctxp[b * Hn + h] + g_ctxp[(Bn + b) * Hn + h]
            + g_ctxp[(2 * Bn + b) * Hn + h] + g_ctxp[(3 * Bn + b) * Hn + h];
    }
    g_xstep[b * KX0 + t] = val;
}

// ---------------- LSTM gates GEMM (j-tile 16, 128 CTAs) --------------------------
__global__ __launch_bounds__(256) void gates_kernel(const float* __restrict__ Xext,
                                                    int xUseScratch, int Kx,
                                                    const float* __restrict__ Wih,
                                                    const float* __restrict__ Hin,
                                                    const float* __restrict__ Whh,
                                                    const float* __restrict__ bi,
                                                    const float* __restrict__ bh) {
    const float* X = xUseScratch ? g_xstep : Xext;
    int j0 = blockIdx.x * 16;
    int tid = threadIdx.x;
    int ty = tid >> 3, tx = tid & 7;
    __shared__ float As[16][128];
    __shared__ float Bs[16][17];
    float acc[4][2];
#pragma unroll
    for (int r = 0; r < 4; r++) { acc[r][0] = 0.f; acc[r][1] = 0.f; }
    for (int ph = 0; ph < 2; ++ph) {
        const float* A = ph ? Hin : X;
        int K = ph ? Hn : Kx;
        const float* W = ph ? Whh : Wih;
        int nkt = K / 16;
        for (int kt = 0; kt < nkt; ++kt) {
            int k0 = kt * 16;
            __syncthreads();
#pragma unroll
            for (int i = 0; i < 2; i++) {
                int idx = tid + i * 256;
                int m = idx >> 2, kq = idx & 3;
                float4 a = *(const float4*)(A + (size_t)m * K + k0 + kq * 4);
                As[kq * 4 + 0][m] = a.x;
                As[kq * 4 + 1][m] = a.y;
                As[kq * 4 + 2][m] = a.z;
                As[kq * 4 + 3][m] = a.w;
            }
            {
                int c = tid >> 4, k = tid & 15;
                Bs[k][c] = W[(size_t)(j0 + c) * K + k0 + k];
            }
            __syncthreads();
#pragma unroll
            for (int k = 0; k < 16; k++) {
                float4 a = *(const float4*)&As[k][ty * 4];
                float b0 = Bs[k][tx * 2], b1 = Bs[k][tx * 2 + 1];
                acc[0][0] += a.x * b0; acc[0][1] += a.x * b1;
                acc[1][0] += a.y * b0; acc[1][1] += a.y * b1;
                acc[2][0] += a.z * b0; acc[2][1] += a.z * b1;
                acc[3][0] += a.w * b0; acc[3][1] += a.w * b1;
            }
        }
    }
#pragma unroll
    for (int r = 0; r < 4; r++) {
        int bb = ty * 4 + r;
#pragma unroll
        for (int c = 0; c < 2; c++) {
            int j = j0 + tx * 2 + c;
            g_gates[bb * G4 + j] = acc[r][c] + bi[j] + bh[j];
        }
    }
}

__global__ void cell_kernel(const float* __restrict__ cprev,
                            float* __restrict__ hout, float* __restrict__ cout) {
    int b = blockIdx.x, h = threadIdx.x;
    const float* g = g_gates + b * G4;
    float ig = sigf(g[h]);
    float fg = sigf(g[Hn + h]);
    float gg = tanh_fast(g[2 * Hn + h]);
    float og = sigf(g[3 * Hn + h]);
    float c = fg * cprev[b * Hn + h] + ig * gg;
    cout[b * Hn + h] = c;
    hout[b * Hn + h] = og * tanh_fast(c);
}

// ---- fused: layer-2 cell + projection ------------------------------------------
__global__ __launch_bounds__(512) void cellproj_kernel(const float* __restrict__ cprev,
                                                       float* __restrict__ hout,
                                                       float* __restrict__ cout,
                                                       const float* __restrict__ pW,
                                                       const float* __restrict__ pb,
                                                       float* __restrict__ out) {
    __shared__ float hs[Hn];
    __shared__ float ps[16][32];
    int b = blockIdx.x, t = threadIdx.x;
    const float* g = g_gates + b * G4;
    float ig = sigf(g[t]);
    float fg = sigf(g[Hn + t]);
    float gg = tanh_fast(g[2 * Hn + t]);
    float og = sigf(g[3 * Hn + t]);
    float c = fg * cprev[b * Hn + t] + ig * gg;
    float hv = og * tanh_fast(c);
    cout[b * Hn + t] = c;
    hout[b * Hn + t] = hv;
    hs[t] = hv;
    __syncthreads();
    int o = t & 31, ck = t >> 5;
    float s = 0.f;
    int k0 = ck * 32;
#pragma unroll 8
    for (int k = k0; k < k0 + 32; k++) s += hs[k] * pW[o * Hn + k];
    ps[ck][o] = s;
    __syncthreads();
    if (t < 32) {
        float a = pb[t];
#pragma unroll
        for (int cc = 0; cc < 16; cc++) a += ps[cc][t];
        out[b * OUTD + t] = a;
    }
}

// ---------------- launcher --------------------------------------------------------
extern "C" void kernel_launch(void* const* d_in, const int* in_sizes, int n_in,
                              void* d_out, int out_size) {
    const float* x      = (const float*)d_in[0];
    const float* h0     = (const float*)d_in[1];
    const float* c0     = (const float*)d_in[2];
    const float* enc    = (const float*)d_in[3];
    const float* attn_W = (const float*)d_in[4];
    const float* attn_b = (const float*)d_in[5];
    const float* v      = (const float*)d_in[6];
    const float* W_ih0  = (const float*)d_in[7];
    const float* W_hh0  = (const float*)d_in[8];
    const float* b_ih0  = (const float*)d_in[9];
    const float* b_hh0  = (const float*)d_in[10];
    const float* W_ih1  = (const float*)d_in[11];
    const float* W_hh1  = (const float*)d_in[12];
    const float* b_ih1  = (const float*)d_in[13];
    const float* b_hh1  = (const float*)d_in[14];
    const float* proj_W = (const float*)d_in[15];
    const float* proj_b = (const float*)d_in[16];

    float* out    = (float*)d_out;
    float* o_out  = out;
    float* o_h1   = out + 4096;
    float* o_h2   = out + 4096 + 65536;
    float* o_c1   = out + 135168;
    float* o_c2   = out + 135168 + 65536;
    float* o_attn = out + 266240;

    cudaFuncSetAttribute(scores_mma_kernel, cudaFuncAttributeMaxDynamicSharedMemorySize, SC_SMEM);

    // launch index 3 = scores (the one ncu captures)
    wesplit_kernel<<<512, 512>>>(attn_W);                        // 0
    zeroflags_kernel<<<1, 4 * 2 * Bn>>>();                       // 1
    hpre_kernel<<<Bn, Hn>>>(h0, attn_W, attn_b);                 // 2
    scores_mma_kernel<<<dim3(4, 2, Bn), 512, SC_SMEM>>>(enc, v); // 3 <- profiled
    softmax_kernel<<<Bn, 256>>>(o_attn);
    context_kernel<<<dim3(4, Bn), Hn>>>(enc, o_attn);
    xstep_kernel<<<Bn, KX0>>>(x);

    gates_kernel<<<G4 / 16, 256>>>(nullptr, 1, KX0, W_ih0, h0, W_hh0, b_ih0, b_hh0);
    cell_kernel<<<Bn, Hn>>>(c0, o_h1, o_c1);
    gates_kernel<<<G4 / 16, 256>>>(o_h1, 0, Hn, W_ih1, h0 + Bn * Hn, W_hh1, b_ih1, b_hh1);
    cellproj_kernel<<<Bn, 512>>>(c0 + Bn * Hn, o_h2, o_c2, proj_W, proj_b, o_out);
}

// round 15
// speedup vs baseline: 1.0179x; 1.0179x over previous
#include <cuda_runtime.h>
#include <cuda_bf16.h>
#include <cstdint>

#define Bn 128
#define Sn 2048
#define Hn 512
#define OUTD 32
#define KX0 544
#define G4 2048

// ---------------- scratch globals ----------------------------------------------
__device__ __align__(16) __nv_bfloat16 g_We_hi[Hn * Hn];   // [h][k]
__device__ __align__(16) __nv_bfloat16 g_We_lo[Hn * Hn];
__device__ __align__(16) uint32_t g_enc_hi[Bn * Sn * Hn / 2];  // bf16x2 packed
__device__ __align__(16) uint32_t g_enc_lo[Bn * Sn * Hn / 2];
__device__ int g_flag[2 * Bn * 4];                          // [region][stile]
__device__ __align__(16) float g_hpre[Bn * Hn];
__device__ __align__(16) float g_scores[4 * Bn * Sn];      // 4 n-quarter partials
__device__ __align__(16) float g_ctxp[4 * Bn * Hn];
__device__ __align__(16) float g_xstep[Bn * KX0];
__device__ __align__(16) float g_gates[Bn * G4];

// ---------------- math helpers ---------------------------------------------------
__device__ __forceinline__ float ex2f(float x) {
    float r; asm("ex2.approx.f32 %0, %1;" : "=f"(r) : "f"(x)); return r;
}
__device__ __forceinline__ float rcpf(float x) {
    float r; asm("rcp.approx.f32 %0, %1;" : "=f"(r) : "f"(x)); return r;
}
__device__ __forceinline__ float tanh_fast(float x) {
    float e = ex2f(x * 2.885390081777927f);
    return 1.0f - 2.0f * rcpf(e + 1.0f);
}
__device__ __forceinline__ float sigf(float x) {
    return rcpf(1.0f + ex2f(-1.4426950408889634f * x));
}
// pack (a,b) -> bf16x2, a in LOW 16 bits
__device__ __forceinline__ uint32_t bf2(float a, float b) {
    uint32_t r; asm("cvt.rn.bf16x2.f32 %0, %1, %2;" : "=r"(r) : "f"(b), "f"(a)); return r;
}
__device__ __forceinline__ uint32_t smem_u32(const void* p) {
    uint32_t a;
    asm("{ .reg .u64 t; cvta.to.shared.u64 t, %1; cvt.u32.u64 %0, t; }" : "=r"(a) : "l"(p));
    return a;
}
__device__ __forceinline__ uint32_t swz128(uint32_t off) { return off ^ ((off >> 3) & 0x70); }

#define CP16(d, s) asm volatile("cp.async.ca.shared.global [%0], [%1], 16;" :: "r"(d), "l"(s))
#define CP_COMMIT() asm volatile("cp.async.commit_group;" ::: "memory")

#define LDSM4(r, a) \
    asm volatile("ldmatrix.sync.aligned.m8n8.x4.shared.b16 {%0,%1,%2,%3}, [%4];" \
        : "=r"((r)[0]), "=r"((r)[1]), "=r"((r)[2]), "=r"((r)[3]) : "r"(a))
#define MMA16816(c, a, b) \
    asm volatile("mma.sync.aligned.m16n8k16.row.col.f32.bf16.bf16.f32 " \
        "{%0,%1,%2,%3}, {%4,%5,%6,%7}, {%8,%9}, {%0,%1,%2,%3};" \
        : "+f"((c)[0]), "+f"((c)[1]), "+f"((c)[2]), "+f"((c)[3]) \
        : "r"((a)[0]), "r"((a)[1]), "r"((a)[2]), "r"((a)[3]), "r"((b)[0]), "r"((b)[1]))

// ---------------- prep kernels ---------------------------------------------------
__global__ void wesplit_kernel(const float* __restrict__ attn_W) {
    int h = blockIdx.x, k = threadIdx.x;
    float x = attn_W[h * 1024 + 512 + k];
    __nv_bfloat16 hi = __float2bfloat16(x);
    g_We_hi[h * Hn + k] = hi;
    g_We_lo[h * Hn + k] = __float2bfloat16(x - __bfloat162float(hi));
}
__global__ void zeroflags_kernel() {
    g_flag[blockIdx.x * 256 + threadIdx.x] = 0;
}

// ---------------- hpre = h0[1] @ W_h^T + attn_b ----------------------------------
__global__ void hpre_kernel(const float* __restrict__ h0, const float* __restrict__ attn_W,
                            const float* __restrict__ attn_b) {
    __shared__ float sh[Hn];
    int b = blockIdx.x, t = threadIdx.x;
    sh[t] = h0[Bn * Hn + b * Hn + t];
    __syncthreads();
    const float4* w = (const float4*)(attn_W + (size_t)t * 1024);
    float acc = attn_b[t];
#pragma unroll 8
    for (int k4 = 0; k4 < 128; k4++) {
        float4 ww = w[k4];
        acc += sh[k4 * 4 + 0] * ww.x + sh[k4 * 4 + 1] * ww.y
             + sh[k4 * 4 + 2] * ww.z + sh[k4 * 4 + 3] * ww.w;
    }
    g_hpre[b * Hn + t] = acc;
}

// ---------------- scores: mma.sync bf16 3-pass + lazy cooperative enc split ------
// CTA (ntile 0..3, sgroup 0..1, b): converts stile 'ntile' of its region, flags it,
// computes stiles in rotated order starting with its own (no upfront wait); peer
// flags checked lazily at the cross-stile prefetch point.
// Per stile: M=256 x N=128, K=512 in 8 chunks of 64. 16 warps 4x4, warp tile 64x32.
// SMEM stage st at st*98304: Ahi 32K | Alo 32K | Bhi 16K | Blo 16K
// misc @196608: v[128] | hpre[128] | row[256]
#define SC_SMEM 198656

__global__ __launch_bounds__(512, 1) void scores_mma_kernel(const float* __restrict__ enc,
                                                            const float* __restrict__ v) {
    extern __shared__ __align__(1024) char smem[];
    uint32_t sb = smem_u32(smem);
    int tid = threadIdx.x;
    int lane = tid & 31, wid = tid >> 5;
    int wm = wid >> 2, wn = wid & 3;
    int ntile = blockIdx.x;          // 0..3 (h-quarter AND own stile id)
    int sgrp  = blockIdx.y;          // 0..1
    int b = blockIdx.z;
    int h0 = ntile * 128;

    float* sh_v    = (float*)(smem + 196608);
    float* sh_hpre = (float*)(smem + 196608 + 512);
    float* sh_row  = (float*)(smem + 196608 + 1024);

    if (tid < 128) {
        sh_v[tid]    = v[h0 + tid];
        sh_hpre[tid] = g_hpre[b * Hn + h0 + tid];
    }
    if (tid < 256) sh_row[tid] = 0.0f;

    int* fl = g_flag + (sgrp * Bn + b) * 4;

    // ---- convert OWN stile (ntile) to bf16 hi/lo, publish flag; no wait ----
    {
        size_t rowbase = (size_t)b * Sn + (size_t)(sgrp * 4 + ntile) * 256;
        const float4* src = (const float4*)enc + rowbase * 128;
        uint2* dh = (uint2*)g_enc_hi + rowbase * 128;
        uint2* dl = (uint2*)g_enc_lo + rowbase * 128;
#pragma unroll 4
        for (int i = tid; i < 32768; i += 512) {
            float4 f = src[i];
            __nv_bfloat16 hx = __float2bfloat16(f.x), hy = __float2bfloat16(f.y);
            __nv_bfloat16 hz = __float2bfloat16(f.z), hw = __float2bfloat16(f.w);
            uint32_t hi0 = bf2(__bfloat162float(hx), __bfloat162float(hy));
            uint32_t hi1 = bf2(__bfloat162float(hz), __bfloat162float(hw));
            uint32_t lo0 = bf2(f.x - __bfloat162float(hx), f.y - __bfloat162float(hy));
            uint32_t lo1 = bf2(f.z - __bfloat162float(hz), f.w - __bfloat162float(hw));
            dh[i] = make_uint2(hi0, hi1);
            dl[i] = make_uint2(lo0, lo1);
        }
        __syncthreads();           // own writes ordered before own cp.async reads
        if (tid == 0) {
            __threadfence();       // publish to GPU scope for peers
            atomicExch(&fl[ntile], 1);
        }
    }

    const char* WH = (const char*)(g_We_hi + (size_t)h0 * Hn);
    const char* WL = (const char*)(g_We_lo + (size_t)h0 * Hn);

    auto encbase = [&](int it) -> size_t {
        int s0 = (sgrp * 4 + it) * 256;
        return ((size_t)(b * Sn + s0)) * 1024;
    };

    auto produce = [&](int it, int c, int st) {
        uint32_t stb = sb + st * 98304;
        uint32_t aH = stb, aL = stb + 32768, bH = stb + 65536, bL = stb + 81920;
        int cb = c * 128;
        const char* EH = (const char*)g_enc_hi + encbase(it);
        const char* EL = (const char*)g_enc_lo + encbase(it);
#pragma unroll
        for (int j = 0; j < 4; j++) {
            int idx = tid + j * 512;
            int r = idx >> 3, seg = idx & 7;
            uint32_t doff = swz128((uint32_t)(r * 128 + seg * 16));
            CP16(aH + doff, EH + (size_t)r * 1024 + cb + seg * 16);
            CP16(aL + doff, EL + (size_t)r * 1024 + cb + seg * 16);
        }
#pragma unroll
        for (int j = 0; j < 2; j++) {
            int idx = tid + j * 512;
            int r = idx >> 3, seg = idx & 7;
            uint32_t doff = swz128((uint32_t)(r * 128 + seg * 16));
            CP16(bH + doff, WH + (size_t)r * 1024 + cb + seg * 16);
            CP16(bL + doff, WL + (size_t)r * 1024 + cb + seg * 16);
        }
        CP_COMMIT();
    };

    int arow = lane & 15;
    int acol = (lane >> 4) * 16;
    int brow4 = ((lane >> 4) << 3) | (lane & 7);
    int bcol  = ((lane >> 3) & 1) * 16;
    int rbase = lane >> 2;
    int q = lane & 3;
    int cbase = q * 2;

    int kctr = 0;
    produce(ntile, 0, 0);          // first stile = own (data just written, visible)

    for (int ii = 0; ii < 4; ii++) {
        int it = (ntile + ii) & 3;
        float acc[4][4][4];
#pragma unroll
        for (int mf = 0; mf < 4; mf++)
#pragma unroll
            for (int nf = 0; nf < 4; nf++)
#pragma unroll
                for (int r = 0; r < 4; r++) acc[mf][nf][r] = 0.0f;

        for (int c = 0; c < 8; c++) {
            int st = kctr & 1;
            asm volatile("cp.async.wait_group 0;" ::: "memory");
            __syncthreads();

            uint32_t stb = sb + st * 98304;
            uint32_t aH = stb, aL = stb + 32768, bH = stb + 65536, bL = stb + 81920;
#pragma unroll
            for (int ks = 0; ks < 4; ks++) {
                uint32_t bh[4][2], bl[4][2];
#pragma unroll
                for (int p = 0; p < 2; p++) {
                    uint32_t off = swz128((uint32_t)((wn * 32 + p * 16 + brow4) * 128 + ks * 32 + bcol));
                    uint32_t t4[4];
                    LDSM4(t4, bH + off);
                    bh[2 * p][0] = t4[0]; bh[2 * p][1] = t4[1];
                    bh[2 * p + 1][0] = t4[2]; bh[2 * p + 1][1] = t4[3];
                    LDSM4(t4, bL + off);
                    bl[2 * p][0] = t4[0]; bl[2 * p][1] = t4[1];
                    bl[2 * p + 1][0] = t4[2]; bl[2 * p + 1][1] = t4[3];
                }
#pragma unroll
                for (int mf = 0; mf < 4; mf++) {
                    uint32_t ah[4], al[4];
                    uint32_t off = swz128((uint32_t)((wm * 64 + mf * 16 + arow) * 128 + ks * 32 + acol));
                    LDSM4(ah, aH + off);
                    LDSM4(al, aL + off);
#pragma unroll
                    for (int nf = 0; nf < 4; nf++) MMA16816(acc[mf][nf], ah, bh[nf]);
#pragma unroll
                    for (int nf = 0; nf < 4; nf++) MMA16816(acc[mf][nf], ah, bl[nf]);
#pragma unroll
                    for (int nf = 0; nf < 4; nf++) MMA16816(acc[mf][nf], al, bh[nf]);
                }
                if (ks == 0) {     // producer hidden under MMAs
                    if (c + 1 < 8) {
                        produce(it, c + 1, st ^ 1);
                    } else if (ii + 1 < 4) {
                        int nxt = (ntile + ii + 1) & 3;
                        // lazy peer-flag wait (first needed here; peer had ~1 stile
                        // of head start; L2-broadcast spin, normally already set)
                        int rdy;
                        do {
                            asm volatile("ld.global.cg.b32 %0, [%1];" : "=r"(rdy) : "l"(fl + nxt));
                        } while (!rdy);
                        produce(nxt, 0, st ^ 1);
                    }
                }
            }
            kctr++;
        }

        // ---- epilogue for this stile ----
        int s0 = (sgrp * 4 + it) * 256;
        __syncthreads();
#pragma unroll
        for (int mf = 0; mf < 4; mf++) {
#pragma unroll
            for (int rr = 0; rr < 2; rr++) {
                int m = wm * 64 + mf * 16 + rbase + rr * 8;
                float p = 0.0f;
#pragma unroll
                for (int nf = 0; nf < 4; nf++) {
                    int n0 = wn * 32 + nf * 8 + cbase;
                    float e0 = acc[mf][nf][rr * 2 + 0] + sh_hpre[n0];
                    float e1 = acc[mf][nf][rr * 2 + 1] + sh_hpre[n0 + 1];
                    p += sh_v[n0] * tanh_fast(e0) + sh_v[n0 + 1] * tanh_fast(e1);
                }
                p += __shfl_xor_sync(0xffffffffu, p, 1);
                p += __shfl_xor_sync(0xffffffffu, p, 2);
                if (q == 0) atomicAdd(&sh_row[m], p);
            }
        }
        __syncthreads();
        if (tid < 256) {
            g_scores[(size_t)ntile * Bn * Sn + (size_t)b * Sn + s0 + tid] = sh_row[tid];
            sh_row[tid] = 0.0f;
        }
    }
}

// ---------------- softmax (sums the 4 n-quarter partials) ------------------------
__global__ void softmax_kernel(float* __restrict__ out_attn) {
    int b = blockIdx.x, t = threadIdx.x;
    float vals[8];
    float m = -1e30f;
#pragma unroll
    for (int i = 0; i < 8; i++) {
        int idx = t + i * 256;
        vals[i] = g_scores[b * Sn + idx]
                + g_scores[Bn * Sn + b * Sn + idx]
                + g_scores[2 * Bn * Sn + b * Sn + idx]
                + g_scores[3 * Bn * Sn + b * Sn + idx];
        m = fmaxf(m, vals[i]);
    }
    __shared__ float red[256];
    red[t] = m; __syncthreads();
    for (int o = 128; o > 0; o >>= 1) {
        if (t < o) red[t] = fmaxf(red[t], red[t + o]);
        __syncthreads();
    }
    m = red[0];
    __syncthreads();
    float sum = 0.f;
#pragma unroll
    for (int i = 0; i < 8; i++) {
        vals[i] = ex2f((vals[i] - m) * 1.4426950408889634f);
        sum += vals[i];
    }
    red[t] = sum; __syncthreads();
    for (int o = 128; o > 0; o >>= 1) {
        if (t < o) red[t] += red[t + o];
        __syncthreads();
    }
    float inv = 1.0f / red[0];
#pragma unroll
    for (int i = 0; i < 8; i++) out_attn[b * Sn + t + i * 256] = vals[i] * inv;
}

// ---------------- context --------------------------------------------------------
__global__ void context_kernel(const float* __restrict__ enc, const float* __restrict__ attn) {
    int sc = blockIdx.x, b = blockIdx.y, h = threadIdx.x;
    __shared__ float w[512];
    w[h] = attn[b * Sn + sc * 512 + h];
    __syncthreads();
    const float* e = enc + ((size_t)(b * Sn + sc * 512)) * Hn + h;
    float acc = 0.f;
#pragma unroll 8
    for (int s = 0; s < 512; s++) acc += w[s] * e[(size_t)s * Hn];
    g_ctxp[(sc * Bn + b) * Hn + h] = acc;
}
__global__ void xstep_kernel(const float* __restrict__ x) {
    int b = blockIdx.x, t = threadIdx.x;
    float val;
    if (t < OUTD) val = x[b * OUTD + t];
    else {
        int h = t - OUTD;
        val = g_ctxp[b * Hn + h] + g_ctxp[(Bn + b) * Hn + h]
            + g_ctxp[(2 * Bn + b) * Hn + h] + g_ctxp[(3 * Bn + b) * Hn + h];
    }
    g_xstep[b * KX0 + t] = val;
}

// ---------------- LSTM gates GEMM (j-tile 16, 128 CTAs) --------------------------
__global__ __launch_bounds__(256) void gates_kernel(const float* __restrict__ Xext,
                                                    int xUseScratch, int Kx,
                                                    const float* __restrict__ Wih,
                                                    const float* __restrict__ Hin,
                                                    const float* __restrict__ Whh,
                                                    const float* __restrict__ bi,
                                                    const float* __restrict__ bh) {
    const float* X = xUseScratch ? g_xstep : Xext;
    int j0 = blockIdx.x * 16;
    int tid = threadIdx.x;
    int ty = tid >> 3, tx = tid & 7;
    __shared__ float As[16][128];
    __shared__ float Bs[16][17];
    float acc[4][2];
#pragma unroll
    for (int r = 0; r < 4; r++) { acc[r][0] = 0.f; acc[r][1] = 0.f; }
    for (int ph = 0; ph < 2; ++ph) {
        const float* A = ph ? Hin : X;
        int K = ph ? Hn : Kx;
        const float* W = ph ? Whh : Wih;
        int nkt = K / 16;
        for (int kt = 0; kt < nkt; ++kt) {
            int k0 = kt * 16;
            __syncthreads();
#pragma unroll
            for (int i = 0; i < 2; i++) {
                int idx = tid + i * 256;
                int m = idx >> 2, kq = idx & 3;
                float4 a = *(const float4*)(A + (size_t)m * K + k0 + kq * 4);
                As[kq * 4 + 0][m] = a.x;
                As[kq * 4 + 1][m] = a.y;
                As[kq * 4 + 2][m] = a.z;
                As[kq * 4 + 3][m] = a.w;
            }
            {
                int c = tid >> 4, k = tid & 15;
                Bs[k][c] = W[(size_t)(j0 + c) * K + k0 + k];
            }
            __syncthreads();
#pragma unroll
            for (int k = 0; k < 16; k++) {
                float4 a = *(const float4*)&As[k][ty * 4];
                float b0 = Bs[k][tx * 2], b1 = Bs[k][tx * 2 + 1];
                acc[0][0] += a.x * b0; acc[0][1] += a.x * b1;
                acc[1][0] += a.y * b0; acc[1][1] += a.y * b1;
                acc[2][0] += a.z * b0; acc[2][1] += a.z * b1;
                acc[3][0] += a.w * b0; acc[3][1] += a.w * b1;
            }
        }
    }
#pragma unroll
    for (int r = 0; r < 4; r++) {
        int bb = ty * 4 + r;
#pragma unroll
        for (int c = 0; c < 2; c++) {
            int j = j0 + tx * 2 + c;
            g_gates[bb * G4 + j] = acc[r][c] + bi[j] + bh[j];
        }
    }
}

__global__ void cell_kernel(const float* __restrict__ cprev,
                            float* __restrict__ hout, float* __restrict__ cout) {
    int b = blockIdx.x, h = threadIdx.x;
    const float* g = g_gates + b * G4;
    float ig = sigf(g[h]);
    float fg = sigf(g[Hn + h]);
    float gg = tanh_fast(g[2 * Hn + h]);
    float og = sigf(g[3 * Hn + h]);
    float c = fg * cprev[b * Hn + h] + ig * gg;
    cout[b * Hn + h] = c;
    hout[b * Hn + h] = og * tanh_fast(c);
}

// ---- fused: layer-2 cell + projection ------------------------------------------
__global__ __launch_bounds__(512) void cellproj_kernel(const float* __restrict__ cprev,
                                                       float* __restrict__ hout,
                                                       float* __restrict__ cout,
                                                       const float* __restrict__ pW,
                                                       const float* __restrict__ pb,
                                                       float* __restrict__ out) {
    __shared__ float hs[Hn];
    __shared__ float ps[16][32];
    int b = blockIdx.x, t = threadIdx.x;
    const float* g = g_gates + b * G4;
    float ig = sigf(g[t]);
    float fg = sigf(g[Hn + t]);
    float gg = tanh_fast(g[2 * Hn + t]);
    float og = sigf(g[3 * Hn + t]);
    float c = fg * cprev[b * Hn + t] + ig * gg;
    float hv = og * tanh_fast(c);
    cout[b * Hn + t] = c;
    hout[b * Hn + t] = hv;
    hs[t] = hv;
    __syncthreads();
    int o = t & 31, ck = t >> 5;
    float s = 0.f;
    int k0 = ck * 32;
#pragma unroll 8
    for (int k = k0; k < k0 + 32; k++) s += hs[k] * pW[o * Hn + k];
    ps[ck][o] = s;
    __syncthreads();
    if (t < 32) {
        float a = pb[t];
#pragma unroll
        for (int cc = 0; cc < 16; cc++) a += ps[cc][t];
        out[b * OUTD + t] = a;
    }
}

// ---------------- launcher --------------------------------------------------------
extern "C" void kernel_launch(void* const* d_in, const int* in_sizes, int n_in,
                              void* d_out, int out_size) {
    const float* x      = (const float*)d_in[0];
    const float* h0     = (const float*)d_in[1];
    const float* c0     = (const float*)d_in[2];
    const float* enc    = (const float*)d_in[3];
    const float* attn_W = (const float*)d_in[4];
    const float* attn_b = (const float*)d_in[5];
    const float* v      = (const float*)d_in[6];
    const float* W_ih0  = (const float*)d_in[7];
    const float* W_hh0  = (const float*)d_in[8];
    const float* b_ih0  = (const float*)d_in[9];
    const float* b_hh0  = (const float*)d_in[10];
    const float* W_ih1  = (const float*)d_in[11];
    const float* W_hh1  = (const float*)d_in[12];
    const float* b_ih1  = (const float*)d_in[13];
    const float* b_hh1  = (const float*)d_in[14];
    const float* proj_W = (const float*)d_in[15];
    const float* proj_b = (const float*)d_in[16];

    float* out    = (float*)d_out;
    float* o_out  = out;
    float* o_h1   = out + 4096;
    float* o_h2   = out + 4096 + 65536;
    float* o_c1   = out + 135168;
    float* o_c2   = out + 135168 + 65536;
    float* o_attn = out + 266240;

    cudaFuncSetAttribute(scores_mma_kernel, cudaFuncAttributeMaxDynamicSharedMemorySize, SC_SMEM);

    // launch index 3 = scores (the one ncu captures)
    wesplit_kernel<<<512, 512>>>(attn_W);                        // 0
    zeroflags_kernel<<<4, 256>>>();                              // 1
    hpre_kernel<<<Bn, Hn>>>(h0, attn_W, attn_b);                 // 2
    scores_mma_kernel<<<dim3(4, 2, Bn), 512, SC_SMEM>>>(enc, v); // 3 <- profiled
    softmax_kernel<<<Bn, 256>>>(o_attn);
    context_kernel<<<dim3(4, Bn), Hn>>>(enc, o_attn);
    xstep_kernel<<<Bn, KX0>>>(x);

    gates_kernel<<<G4 / 16, 256>>>(nullptr, 1, KX0, W_ih0, h0, W_hh0, b_ih0, b_hh0);
    cell_kernel<<<Bn, Hn>>>(c0, o_h1, o_c1);
    gates_kernel<<<G4 / 16, 256>>>(o_h1, 0, Hn, W_ih1, h0 + Bn * Hn, W_hh1, b_ih1, b_hh1);
    cellproj_kernel<<<Bn, 512>>>(c0 + Bn * Hn, o_h2, o_c2, proj_W, proj_b, o_out);
}